// round 6
// baseline (speedup 1.0000x reference)
#include <cuda_runtime.h>

#define BSZ 8
#define QL  128
#define NS1 32
#define NS2 64
#define HD  768
#define NHD 12
#define DH  64
#define SCALE 0.125f   // 1/sqrt(64)

// ---------------- scratch (device globals; no allocations allowed) ----------
__device__ float g_Qp [BSZ*QL*HD];           // word-attn Q proj
__device__ float g_SQ [BSZ*QL*HD];           // sentence Q proj
__device__ float g_Kp [BSZ*NS1*NS2*HD];      // word K proj
__device__ float g_Vp [BSZ*NS1*NS2*HD];      // word V proj
__device__ float g_SK [BSZ*NS1*HD];          // sentence K proj
__device__ float g_WH [BSZ*QL*NS1*HD];       // word hidden  [b,q,s,768]
__device__ float g_P2 [BSZ*QL*NHD*NS1];      // sentence probs
__device__ float g_CTX[BSZ*QL*NHD*HD];       // ctx = sum_s p2*wh  [b,q,h,768]

// ---------------- generic projection GEMM: C[M,768] = A[M,768]@B[768,768]+bias
// tile 64(M) x 128(N), K-step 16, 256 threads, 4x8 microtile
__global__ __launch_bounds__(256) void sgemm128_bias(
    const float* __restrict__ A, const float* __restrict__ B,
    const float* __restrict__ bias, float* __restrict__ C, int M)
{
    __shared__ float As[16][68];    // [k][m], padded
    __shared__ float Bs[16][128];   // [k][n]

    const int tid = threadIdx.x;
    const int tr  = tid >> 4;          // 0..15 -> rows tr*4..
    const int tc  = tid & 15;          // 0..15 -> cols tc*8..
    const int m0  = blockIdx.y * 64;
    const int n0  = blockIdx.x * 128;

    const int lr = tid >> 2;           // A load row 0..63
    const int lk = (tid & 3) << 2;     // A load k   0,4,8,12
    const int bk = tid >> 4;           // B load k row 0..15
    const int bn = (tid & 15) << 3;    // B load col 0..120

    float acc[4][8];
    #pragma unroll
    for (int i = 0; i < 4; i++)
        #pragma unroll
        for (int j = 0; j < 8; j++) acc[i][j] = 0.f;

    for (int k0 = 0; k0 < 768; k0 += 16) {
        float4 av = *(const float4*)(A + (size_t)(m0 + lr) * 768 + k0 + lk);
        As[lk + 0][lr] = av.x; As[lk + 1][lr] = av.y;
        As[lk + 2][lr] = av.z; As[lk + 3][lr] = av.w;
        const float* bp = B + (size_t)(k0 + bk) * 768 + n0 + bn;
        *(float4*)&Bs[bk][bn]     = *(const float4*)(bp);
        *(float4*)&Bs[bk][bn + 4] = *(const float4*)(bp + 4);
        __syncthreads();
        #pragma unroll
        for (int kk = 0; kk < 16; kk++) {
            float4 a = *(const float4*)&As[kk][tr << 2];
            float4 u = *(const float4*)&Bs[kk][tc << 3];
            float4 v = *(const float4*)&Bs[kk][(tc << 3) + 4];
            float ar[4] = {a.x, a.y, a.z, a.w};
            float br[8] = {u.x, u.y, u.z, u.w, v.x, v.y, v.z, v.w};
            #pragma unroll
            for (int i = 0; i < 4; i++)
                #pragma unroll
                for (int j = 0; j < 8; j++)
                    acc[i][j] = fmaf(ar[i], br[j], acc[i][j]);
        }
        __syncthreads();
    }
    #pragma unroll
    for (int i = 0; i < 4; i++) {
        int row = m0 + (tr << 2) + i;
        float* cp = C + (size_t)row * 768 + n0 + (tc << 3);
        const float* bb = bias + n0 + (tc << 3);
        float4 o0, o1;
        o0.x = acc[i][0] + bb[0]; o0.y = acc[i][1] + bb[1];
        o0.z = acc[i][2] + bb[2]; o0.w = acc[i][3] + bb[3];
        o1.x = acc[i][4] + bb[4]; o1.y = acc[i][5] + bb[5];
        o1.z = acc[i][6] + bb[6]; o1.w = acc[i][7] + bb[7];
        *(float4*)(cp)     = o0;
        *(float4*)(cp + 4) = o1;
    }
}

// ---------------- word attention: one block per (b, s, h) -------------------
// S = softmax(Q K^T * scale + wm) ; WH_slice = S V
#define PADQ 129
#define PADS 65
#define WATTN_SMEM ((64*PADQ + 64*PADS + 64*PADS + 128*PADS) * 4)

__global__ __launch_bounds__(256) void word_attn_kernel(
    const float* __restrict__ Qp, const float* __restrict__ Kp,
    const float* __restrict__ Vp, const int* __restrict__ wmask,
    float* __restrict__ WH)
{
    extern __shared__ float smf[];
    float* Qs = smf;                     // [d][q]  64 x PADQ
    float* Ks = Qs + 64 * PADQ;          // [d][t]  64 x PADS
    float* Vs = Ks + 64 * PADS;          // [t][d]  64 x PADS
    float* S  = Vs + 64 * PADS;          // [q][t] 128 x PADS

    const int h = blockIdx.x, s = blockIdx.y, b = blockIdx.z;
    const int tid = threadIdx.x;

    const float* qbase = Qp + (size_t)b * QL * HD + h * DH;
    for (int idx = tid; idx < QL * DH; idx += 256) {
        int q = idx >> 6, d = idx & 63;
        Qs[d * PADQ + q] = qbase[(size_t)q * HD + d];
    }
    const size_t kvoff = (((size_t)b * NS1 + s) * NS2) * HD + h * DH;
    for (int idx = tid; idx < NS2 * DH; idx += 256) {
        int t = idx >> 6, d = idx & 63;
        size_t g = kvoff + (size_t)t * HD + d;
        Ks[d * PADS + t] = Kp[g];
        Vs[t * PADS + d] = Vp[g];
    }
    __syncthreads();

    const int tr = tid >> 3;   // 0..31 -> q rows tr*4..
    const int tc = tid & 7;    // 0..7  -> t cols tc*8..

    float acc[4][8];
    #pragma unroll
    for (int i = 0; i < 4; i++)
        #pragma unroll
        for (int j = 0; j < 8; j++) acc[i][j] = 0.f;

    for (int d = 0; d < 64; d++) {
        float qr[4], kr[8];
        #pragma unroll
        for (int i = 0; i < 4; i++) qr[i] = Qs[d * PADQ + (tr << 2) + i];
        #pragma unroll
        for (int j = 0; j < 8; j++) kr[j] = Ks[d * PADS + (tc << 3) + j];
        #pragma unroll
        for (int i = 0; i < 4; i++)
            #pragma unroll
            for (int j = 0; j < 8; j++)
                acc[i][j] = fmaf(qr[i], kr[j], acc[i][j]);
    }
    const int* wmrow = wmask + ((size_t)b * NS1 + s) * NS2;
    float wmv[8];
    #pragma unroll
    for (int j = 0; j < 8; j++)
        wmv[j] = (1.f - (float)wmrow[(tc << 3) + j]) * -10000.f;
    #pragma unroll
    for (int i = 0; i < 4; i++)
        #pragma unroll
        for (int j = 0; j < 8; j++)
            S[((tr << 2) + i) * PADS + (tc << 3) + j] = acc[i][j] * SCALE + wmv[j];
    __syncthreads();

    if (tid < 128) {
        float* row = S + tid * PADS;
        float m = row[0];
        #pragma unroll
        for (int t = 1; t < 64; t++) m = fmaxf(m, row[t]);
        float sum = 0.f;
        #pragma unroll
        for (int t = 0; t < 64; t++) { float e = __expf(row[t] - m); row[t] = e; sum += e; }
        float inv = 1.f / sum;
        #pragma unroll
        for (int t = 0; t < 64; t++) row[t] *= inv;
    }
    __syncthreads();

    float o[4][8];
    #pragma unroll
    for (int i = 0; i < 4; i++)
        #pragma unroll
        for (int j = 0; j < 8; j++) o[i][j] = 0.f;
    for (int t = 0; t < 64; t++) {
        float pr[4], vr[8];
        #pragma unroll
        for (int i = 0; i < 4; i++) pr[i] = S[((tr << 2) + i) * PADS + t];
        #pragma unroll
        for (int j = 0; j < 8; j++) vr[j] = Vs[t * PADS + (tc << 3) + j];
        #pragma unroll
        for (int i = 0; i < 4; i++)
            #pragma unroll
            for (int j = 0; j < 8; j++)
                o[i][j] = fmaf(pr[i], vr[j], o[i][j]);
    }
    __syncthreads();
    #pragma unroll
    for (int i = 0; i < 4; i++)
        #pragma unroll
        for (int j = 0; j < 8; j++)
            S[((tr << 2) + i) * PADS + (tc << 3) + j] = o[i][j];
    __syncthreads();

    // coalesced writeout: WH[((b*128+q)*32+s)*768 + h*64 + d]
    float* whbase = WH + (((size_t)b * QL) * NS1 + s) * HD + h * DH;
    for (int idx = tid; idx < QL * DH; idx += 256) {
        int q = idx >> 6, d = idx & 63;
        whbase[(size_t)q * NS1 * HD + d] = S[q * PADS + d];
    }
}

// ---------------- sentence probs: block per (h, b) --------------------------
__global__ __launch_bounds__(256) void sent_probs_kernel(
    const float* __restrict__ SQ, const float* __restrict__ SK,
    const int* __restrict__ smask, float* __restrict__ P2)
{
    __shared__ float SKs[32 * 65];
    __shared__ float SQs[8 * 64];
    const int h = blockIdx.x, b = blockIdx.y;
    const int tid = threadIdx.x;

    for (int idx = tid; idx < 32 * 64; idx += 256) {
        int s_ = idx >> 6, d = idx & 63;
        SKs[s_ * 65 + d] = SK[((size_t)b * NS1 + s_) * HD + h * DH + d];
    }
    const int lane = tid & 31, qi = tid >> 5;
    for (int qt = 0; qt < 16; qt++) {
        __syncthreads();
        for (int idx = tid; idx < 8 * 64; idx += 256) {
            int qq = idx >> 6, d = idx & 63;
            SQs[qq * 64 + d] = SQ[((size_t)b * QL + qt * 8 + qq) * HD + h * DH + d];
        }
        __syncthreads();
        int q = qt * 8 + qi;
        float sc = 0.f;
        #pragma unroll
        for (int d = 0; d < 64; d++)
            sc = fmaf(SQs[qi * 64 + d], SKs[lane * 65 + d], sc);
        sc = sc * SCALE +
             (1.f - (float)smask[((size_t)b * QL + q) * NS1 + lane]) * -10000.f;
        float m = sc;
        #pragma unroll
        for (int o = 16; o > 0; o >>= 1) m = fmaxf(m, __shfl_xor_sync(0xffffffffu, m, o));
        float e = __expf(sc - m);
        float sum = e;
        #pragma unroll
        for (int o = 16; o > 0; o >>= 1) sum += __shfl_xor_sync(0xffffffffu, sum, o);
        P2[(((size_t)b * QL + q) * NHD + h) * NS1 + lane] = e / sum;
    }
}

// ---------------- ctx[b,q,h,c] = sum_s p2[b,q,h,s] * wh[b,q,s,c] -------------
__global__ __launch_bounds__(256) void ctx_kernel(
    const float* __restrict__ WH, const float* __restrict__ P2,
    float* __restrict__ CTX)
{
    __shared__ float p2s[NHD * NS1];
    const int bq = blockIdx.x;   // 0..1023
    const int tid = threadIdx.x;
    for (int idx = tid; idx < NHD * NS1; idx += 256)
        p2s[idx] = P2[(size_t)bq * NHD * NS1 + idx];
    __syncthreads();
    const float* whb = WH + (size_t)bq * NS1 * HD;
    float* ctxb = CTX + (size_t)bq * NHD * HD;
    for (int cc = 0; cc < HD; cc += 256) {
        int c = cc + tid;
        float acc[NHD];
        #pragma unroll
        for (int hh = 0; hh < NHD; hh++) acc[hh] = 0.f;
        for (int s = 0; s < NS1; s++) {
            float w = whb[(size_t)s * HD + c];
            #pragma unroll
            for (int hh = 0; hh < NHD; hh++)
                acc[hh] = fmaf(p2s[hh * NS1 + s], w, acc[hh]);
        }
        #pragma unroll
        for (int hh = 0; hh < NHD; hh++) ctxb[(size_t)hh * HD + c] = acc[hh];
    }
}

// ---------------- final head-sliced GEMM: block per (mtile, h) --------------
// out[r, h*64+n] = sum_k CTX[r, h, k] * W[k, h*64+n] + bias[h*64+n]
__global__ __launch_bounds__(256) void final_proj_kernel(
    const float* __restrict__ CTX, const float* __restrict__ W,
    const float* __restrict__ bias, float* __restrict__ OUT)
{
    __shared__ float As[16][68];
    __shared__ float Bs[16][64];
    const int tid = threadIdx.x;
    const int tr = tid >> 4;          // rows tr*4..
    const int tc = tid & 15;          // cols tc*4..
    const int m0 = blockIdx.x * 64;
    const int h  = blockIdx.y;

    const int lr = tid >> 2;
    const int lk = (tid & 3) << 2;
    const int bk = tid >> 4;
    const int bn = (tid & 15) << 2;

    float acc[4][4];
    #pragma unroll
    for (int i = 0; i < 4; i++)
        #pragma unroll
        for (int j = 0; j < 4; j++) acc[i][j] = 0.f;

    for (int k0 = 0; k0 < 768; k0 += 16) {
        float4 av = *(const float4*)(CTX + (size_t)(m0 + lr) * (NHD * HD) + h * HD + k0 + lk);
        As[lk + 0][lr] = av.x; As[lk + 1][lr] = av.y;
        As[lk + 2][lr] = av.z; As[lk + 3][lr] = av.w;
        *(float4*)&Bs[bk][bn] =
            *(const float4*)(W + (size_t)(k0 + bk) * 768 + h * DH + bn);
        __syncthreads();
        #pragma unroll
        for (int kk = 0; kk < 16; kk++) {
            float4 a = *(const float4*)&As[kk][tr << 2];
            float4 bv = *(const float4*)&Bs[kk][tc << 2];
            float ar[4] = {a.x, a.y, a.z, a.w};
            float br[4] = {bv.x, bv.y, bv.z, bv.w};
            #pragma unroll
            for (int i = 0; i < 4; i++)
                #pragma unroll
                for (int j = 0; j < 4; j++)
                    acc[i][j] = fmaf(ar[i], br[j], acc[i][j]);
        }
        __syncthreads();
    }
    #pragma unroll
    for (int i = 0; i < 4; i++) {
        int row = m0 + (tr << 2) + i;
        float* cp = OUT + (size_t)row * 768 + h * DH + (tc << 2);
        const float* bb = bias + h * DH + (tc << 2);
        float4 o;
        o.x = acc[i][0] + bb[0]; o.y = acc[i][1] + bb[1];
        o.z = acc[i][2] + bb[2]; o.w = acc[i][3] + bb[3];
        *(float4*)cp = o;
    }
}

// ---------------- launch ------------------------------------------------------
extern "C" void kernel_launch(void* const* d_in, const int* in_sizes, int n_in,
                              void* d_out, int out_size)
{
    const float* q_in  = (const float*)d_in[0];
    const float* k_in  = (const float*)d_in[1];
    const float* v_in  = (const float*)d_in[2];
    const float* kvec  = (const float*)d_in[3];
    const int*   wmask = (const int*)d_in[4];
    const int*   smask = (const int*)d_in[5];
    const float* wq_w = (const float*)d_in[6],  *wq_b = (const float*)d_in[7];
    const float* wk_w = (const float*)d_in[8],  *wk_b = (const float*)d_in[9];
    const float* wv_w = (const float*)d_in[10], *wv_b = (const float*)d_in[11];
    const float* sq_w = (const float*)d_in[12], *sq_b = (const float*)d_in[13];
    const float* sk_w = (const float*)d_in[14], *sk_b = (const float*)d_in[15];
    const float* sv_w = (const float*)d_in[16], *sv_b = (const float*)d_in[17];
    float* out = (float*)d_out;

    float *Qp, *SQ, *Kp, *Vp, *SK, *WH, *P2, *CTX;
    cudaGetSymbolAddress((void**)&Qp,  g_Qp);
    cudaGetSymbolAddress((void**)&SQ,  g_SQ);
    cudaGetSymbolAddress((void**)&Kp,  g_Kp);
    cudaGetSymbolAddress((void**)&Vp,  g_Vp);
    cudaGetSymbolAddress((void**)&SK,  g_SK);
    cudaGetSymbolAddress((void**)&WH,  g_WH);
    cudaGetSymbolAddress((void**)&P2,  g_P2);
    cudaGetSymbolAddress((void**)&CTX, g_CTX);

    cudaFuncSetAttribute(word_attn_kernel,
                         cudaFuncAttributeMaxDynamicSharedMemorySize, WATTN_SMEM);

    dim3 blk(256);
    // projections
    sgemm128_bias<<<dim3(6, 16),  blk>>>(q_in, wq_w, wq_b, Qp, BSZ * QL);
    sgemm128_bias<<<dim3(6, 16),  blk>>>(q_in, sq_w, sq_b, SQ, BSZ * QL);
    sgemm128_bias<<<dim3(6, 256), blk>>>(k_in, wk_w, wk_b, Kp, BSZ * NS1 * NS2);
    sgemm128_bias<<<dim3(6, 256), blk>>>(v_in, wv_w, wv_b, Vp, BSZ * NS1 * NS2);
    sgemm128_bias<<<dim3(6, 4),   blk>>>(kvec, sk_w, sk_b, SK, BSZ * NS1);
    // word attention -> WH
    word_attn_kernel<<<dim3(NHD, NS1, BSZ), blk, WATTN_SMEM>>>(Qp, Kp, Vp, wmask, WH);
    // sentence probs -> P2
    sent_probs_kernel<<<dim3(NHD, BSZ), blk>>>(SQ, SK, smask, P2);
    // ctx = sum_s p2 * wh
    ctx_kernel<<<BSZ * QL, blk>>>(WH, P2, CTX);
    // out = ctx @ sv_w (head-sliced) + sv_b
    final_proj_kernel<<<dim3(16, NHD), blk>>>(CTX, sv_w, sv_b, out);
}

// round 7
// speedup vs baseline: 1.6658x; 1.6658x over previous
#include <cuda_runtime.h>

#define BSZ 8
#define QL  128
#define NS1 32
#define NS2 64
#define HD  768
#define NHD 12
#define DH  64
#define SCALE 0.125f   // 1/sqrt(64)

// ---------------- scratch (device globals; no allocations allowed) ----------
__device__ float g_Qp [BSZ*QL*HD];           // word-attn Q proj
__device__ float g_SQ [BSZ*QL*HD];           // sentence Q proj
__device__ float g_Kp [BSZ*NS1*NS2*HD];      // word K proj
__device__ float g_Vp [BSZ*NS1*NS2*HD];      // word V proj
__device__ float g_SK [BSZ*NS1*HD];          // sentence K proj
__device__ float g_WH [BSZ*QL*NS1*HD];       // word hidden  [b,q,s,768]
__device__ float g_P2 [BSZ*QL*NHD*NS1];      // sentence probs
__device__ float g_CTX[BSZ*QL*NHD*HD];       // ctx = sum_s p2*wh  [b,q,h,768]

// ============================================================================
// Fused projection GEMMs: C[M,768] = A[M,768] @ B[768,768] + bias
// 128x128 tile, BK=8, 8x8 microtile, double-buffered smem, cp.async for B.
// blockIdx.z selects one of 5 jobs.
// ============================================================================
struct GemmJob {
    const float* A;
    const float* B;
    const float* bias;
    float*       C;
    int          M;
};
struct GemmJobs { GemmJob j[5]; };

__device__ __forceinline__ void cpa16(void* s, const void* g) {
    unsigned sa = (unsigned)__cvta_generic_to_shared(s);
    asm volatile("cp.async.cg.shared.global [%0], [%1], 16;\n" :: "r"(sa), "l"(g));
}
__device__ __forceinline__ void cpa_commit() {
    asm volatile("cp.async.commit_group;\n" ::: "memory");
}
__device__ __forceinline__ void cpa_wait0() {
    asm volatile("cp.async.wait_group 0;\n" ::: "memory");
}

__global__ __launch_bounds__(256, 2) void sgemm_fused(GemmJobs jobs)
{
    const GemmJob jb = jobs.j[blockIdx.z];
    const int m0 = blockIdx.y * 128;
    if (m0 >= jb.M) return;
    const int n0 = blockIdx.x * 128;

    __shared__ float As[2][8][132];   // [k][m], padded (132%32==4 -> STS conflict-free)
    __shared__ float Bs[2][8][128];   // [k][n]

    const int tid = threadIdx.x;
    const int lr = tid >> 1;            // A load row 0..127
    const int lk = (tid & 1) << 2;      // A load k 0 or 4
    const int bk = tid >> 5;            // B load k row 0..7
    const int bn = (tid & 31) << 2;     // B load col 0..124
    const int tx = tid & 15;            // micro col group
    const int ty = tid >> 4;            // micro row group

    const float* aP = jb.A + (size_t)(m0 + lr) * 768 + lk;
    const float* bP = jb.B + (size_t)bk * 768 + n0 + bn;

    float acc[8][8];
    #pragma unroll
    for (int i = 0; i < 8; i++)
        #pragma unroll
        for (int j = 0; j < 8; j++) acc[i][j] = 0.f;

    // prologue: fill buffer 0
    {
        float4 av = *(const float4*)aP;
        As[0][lk + 0][lr] = av.x; As[0][lk + 1][lr] = av.y;
        As[0][lk + 2][lr] = av.z; As[0][lk + 3][lr] = av.w;
        cpa16(&Bs[0][bk][bn], bP);
        cpa_commit();
        cpa_wait0();
    }
    __syncthreads();

    int buf = 0;
    for (int k0 = 0; k0 < 768; k0 += 8) {
        const int nk = k0 + 8;
        float4 avn;
        if (nk < 768) {
            avn = *(const float4*)(aP + nk);
            cpa16(&Bs[buf ^ 1][bk][bn], bP + (size_t)nk * 768);
            cpa_commit();
        }
        #pragma unroll
        for (int kk = 0; kk < 8; kk++) {
            float4 a0 = *(const float4*)&As[buf][kk][ty << 2];
            float4 a1 = *(const float4*)&As[buf][kk][64 + (ty << 2)];
            float4 b0 = *(const float4*)&Bs[buf][kk][tx << 2];
            float4 b1 = *(const float4*)&Bs[buf][kk][64 + (tx << 2)];
            float ar[8] = {a0.x, a0.y, a0.z, a0.w, a1.x, a1.y, a1.z, a1.w};
            float br[8] = {b0.x, b0.y, b0.z, b0.w, b1.x, b1.y, b1.z, b1.w};
            #pragma unroll
            for (int i = 0; i < 8; i++)
                #pragma unroll
                for (int j = 0; j < 8; j++)
                    acc[i][j] = fmaf(ar[i], br[j], acc[i][j]);
        }
        if (nk < 768) {
            As[buf ^ 1][lk + 0][lr] = avn.x;
            As[buf ^ 1][lk + 1][lr] = avn.y;
            As[buf ^ 1][lk + 2][lr] = avn.z;
            As[buf ^ 1][lk + 3][lr] = avn.w;
            cpa_wait0();
        }
        __syncthreads();
        buf ^= 1;
    }

    // epilogue with bias
    const float* bb = jb.bias + n0;
    float4 bi0 = *(const float4*)(bb + (tx << 2));
    float4 bi1 = *(const float4*)(bb + 64 + (tx << 2));
    #pragma unroll
    for (int i = 0; i < 8; i++) {
        int row = m0 + ((i < 4) ? ((ty << 2) + i) : (64 + (ty << 2) + i - 4));
        float* cp = jb.C + (size_t)row * 768 + n0;
        float4 o0, o1;
        o0.x = acc[i][0] + bi0.x; o0.y = acc[i][1] + bi0.y;
        o0.z = acc[i][2] + bi0.z; o0.w = acc[i][3] + bi0.w;
        o1.x = acc[i][4] + bi1.x; o1.y = acc[i][5] + bi1.y;
        o1.z = acc[i][6] + bi1.z; o1.w = acc[i][7] + bi1.w;
        *(float4*)(cp + (tx << 2))      = o0;
        *(float4*)(cp + 64 + (tx << 2)) = o1;
    }
}

// ---------------- word attention: one block per (b, s, h) -------------------
#define PADQ 129
#define PADS 65
#define WATTN_SMEM ((64*PADQ + 64*PADS + 64*PADS + 128*PADS) * 4)

__global__ __launch_bounds__(256) void word_attn_kernel(
    const float* __restrict__ Qp, const float* __restrict__ Kp,
    const float* __restrict__ Vp, const int* __restrict__ wmask,
    float* __restrict__ WH)
{
    extern __shared__ float smf[];
    float* Qs = smf;                     // [d][q]  64 x PADQ
    float* Ks = Qs + 64 * PADQ;          // [d][t]  64 x PADS
    float* Vs = Ks + 64 * PADS;          // [t][d]  64 x PADS
    float* S  = Vs + 64 * PADS;          // [q][t] 128 x PADS

    const int h = blockIdx.x, s = blockIdx.y, b = blockIdx.z;
    const int tid = threadIdx.x;

    const float* qbase = Qp + (size_t)b * QL * HD + h * DH;
    for (int idx = tid; idx < QL * DH; idx += 256) {
        int q = idx >> 6, d = idx & 63;
        Qs[d * PADQ + q] = qbase[(size_t)q * HD + d];
    }
    const size_t kvoff = (((size_t)b * NS1 + s) * NS2) * HD + h * DH;
    for (int idx = tid; idx < NS2 * DH; idx += 256) {
        int t = idx >> 6, d = idx & 63;
        size_t g = kvoff + (size_t)t * HD + d;
        Ks[d * PADS + t] = Kp[g];
        Vs[t * PADS + d] = Vp[g];
    }
    __syncthreads();

    const int tr = tid >> 3;   // 0..31 -> q rows tr*4..
    const int tc = tid & 7;    // 0..7  -> t cols tc*8..

    float acc[4][8];
    #pragma unroll
    for (int i = 0; i < 4; i++)
        #pragma unroll
        for (int j = 0; j < 8; j++) acc[i][j] = 0.f;

    for (int d = 0; d < 64; d++) {
        float qr[4], kr[8];
        #pragma unroll
        for (int i = 0; i < 4; i++) qr[i] = Qs[d * PADQ + (tr << 2) + i];
        #pragma unroll
        for (int j = 0; j < 8; j++) kr[j] = Ks[d * PADS + (tc << 3) + j];
        #pragma unroll
        for (int i = 0; i < 4; i++)
            #pragma unroll
            for (int j = 0; j < 8; j++)
                acc[i][j] = fmaf(qr[i], kr[j], acc[i][j]);
    }
    const int* wmrow = wmask + ((size_t)b * NS1 + s) * NS2;
    float wmv[8];
    #pragma unroll
    for (int j = 0; j < 8; j++)
        wmv[j] = (1.f - (float)wmrow[(tc << 3) + j]) * -10000.f;
    #pragma unroll
    for (int i = 0; i < 4; i++)
        #pragma unroll
        for (int j = 0; j < 8; j++)
            S[((tr << 2) + i) * PADS + (tc << 3) + j] = acc[i][j] * SCALE + wmv[j];
    __syncthreads();

    if (tid < 128) {
        float* row = S + tid * PADS;
        float m = row[0];
        #pragma unroll
        for (int t = 1; t < 64; t++) m = fmaxf(m, row[t]);
        float sum = 0.f;
        #pragma unroll
        for (int t = 0; t < 64; t++) { float e = __expf(row[t] - m); row[t] = e; sum += e; }
        float inv = 1.f / sum;
        #pragma unroll
        for (int t = 0; t < 64; t++) row[t] *= inv;
    }
    __syncthreads();

    float o[4][8];
    #pragma unroll
    for (int i = 0; i < 4; i++)
        #pragma unroll
        for (int j = 0; j < 8; j++) o[i][j] = 0.f;
    for (int t = 0; t < 64; t++) {
        float pr[4], vr[8];
        #pragma unroll
        for (int i = 0; i < 4; i++) pr[i] = S[((tr << 2) + i) * PADS + t];
        #pragma unroll
        for (int j = 0; j < 8; j++) vr[j] = Vs[t * PADS + (tc << 3) + j];
        #pragma unroll
        for (int i = 0; i < 4; i++)
            #pragma unroll
            for (int j = 0; j < 8; j++)
                o[i][j] = fmaf(pr[i], vr[j], o[i][j]);
    }
    __syncthreads();
    #pragma unroll
    for (int i = 0; i < 4; i++)
        #pragma unroll
        for (int j = 0; j < 8; j++)
            S[((tr << 2) + i) * PADS + (tc << 3) + j] = o[i][j];
    __syncthreads();

    float* whbase = WH + (((size_t)b * QL) * NS1 + s) * HD + h * DH;
    for (int idx = tid; idx < QL * DH; idx += 256) {
        int q = idx >> 6, d = idx & 63;
        whbase[(size_t)q * NS1 * HD + d] = S[q * PADS + d];
    }
}

// ---------------- sentence probs: block per (h, b) --------------------------
__global__ __launch_bounds__(256) void sent_probs_kernel(
    const float* __restrict__ SQ, const float* __restrict__ SK,
    const int* __restrict__ smask, float* __restrict__ P2)
{
    __shared__ float SKs[32 * 65];
    __shared__ float SQs[8 * 64];
    const int h = blockIdx.x, b = blockIdx.y;
    const int tid = threadIdx.x;

    for (int idx = tid; idx < 32 * 64; idx += 256) {
        int s_ = idx >> 6, d = idx & 63;
        SKs[s_ * 65 + d] = SK[((size_t)b * NS1 + s_) * HD + h * DH + d];
    }
    const int lane = tid & 31, qi = tid >> 5;
    for (int qt = 0; qt < 16; qt++) {
        __syncthreads();
        for (int idx = tid; idx < 8 * 64; idx += 256) {
            int qq = idx >> 6, d = idx & 63;
            SQs[qq * 64 + d] = SQ[((size_t)b * QL + qt * 8 + qq) * HD + h * DH + d];
        }
        __syncthreads();
        int q = qt * 8 + qi;
        float sc = 0.f;
        #pragma unroll
        for (int d = 0; d < 64; d++)
            sc = fmaf(SQs[qi * 64 + d], SKs[lane * 65 + d], sc);
        sc = sc * SCALE +
             (1.f - (float)smask[((size_t)b * QL + q) * NS1 + lane]) * -10000.f;
        float m = sc;
        #pragma unroll
        for (int o = 16; o > 0; o >>= 1) m = fmaxf(m, __shfl_xor_sync(0xffffffffu, m, o));
        float e = __expf(sc - m);
        float sum = e;
        #pragma unroll
        for (int o = 16; o > 0; o >>= 1) sum += __shfl_xor_sync(0xffffffffu, sum, o);
        P2[(((size_t)b * QL + q) * NHD + h) * NS1 + lane] = e / sum;
    }
}

// ---------------- ctx[b,q,h,c] = sum_s p2[b,q,h,s] * wh[b,q,s,c] -------------
__global__ __launch_bounds__(256) void ctx_kernel(
    const float* __restrict__ WH, const float* __restrict__ P2,
    float* __restrict__ CTX)
{
    __shared__ float p2s[NHD * NS1];
    const int bq = blockIdx.x;   // 0..1023
    const int tid = threadIdx.x;
    for (int idx = tid; idx < NHD * NS1; idx += 256)
        p2s[idx] = P2[(size_t)bq * NHD * NS1 + idx];
    __syncthreads();
    const float* whb = WH + (size_t)bq * NS1 * HD;
    float* ctxb = CTX + (size_t)bq * NHD * HD;
    for (int cc = 0; cc < HD; cc += 256) {
        int c = cc + tid;
        float acc[NHD];
        #pragma unroll
        for (int hh = 0; hh < NHD; hh++) acc[hh] = 0.f;
        for (int s = 0; s < NS1; s++) {
            float w = whb[(size_t)s * HD + c];
            #pragma unroll
            for (int hh = 0; hh < NHD; hh++)
                acc[hh] = fmaf(p2s[hh * NS1 + s], w, acc[hh]);
        }
        #pragma unroll
        for (int hh = 0; hh < NHD; hh++) ctxb[(size_t)hh * HD + c] = acc[hh];
    }
}

// ---------------- final head-sliced GEMM: block per (mtile, h) --------------
__global__ __launch_bounds__(256) void final_proj_kernel(
    const float* __restrict__ CTX, const float* __restrict__ W,
    const float* __restrict__ bias, float* __restrict__ OUT)
{
    __shared__ float As[16][68];
    __shared__ float Bs[16][64];
    const int tid = threadIdx.x;
    const int tr = tid >> 4;
    const int tc = tid & 15;
    const int m0 = blockIdx.x * 64;
    const int h  = blockIdx.y;

    const int lr = tid >> 2;
    const int lk = (tid & 3) << 2;
    const int bk = tid >> 4;
    const int bn = (tid & 15) << 2;

    float acc[4][4];
    #pragma unroll
    for (int i = 0; i < 4; i++)
        #pragma unroll
        for (int j = 0; j < 4; j++) acc[i][j] = 0.f;

    for (int k0 = 0; k0 < 768; k0 += 16) {
        float4 av = *(const float4*)(CTX + (size_t)(m0 + lr) * (NHD * HD) + h * HD + k0 + lk);
        As[lk + 0][lr] = av.x; As[lk + 1][lr] = av.y;
        As[lk + 2][lr] = av.z; As[lk + 3][lr] = av.w;
        *(float4*)&Bs[bk][bn] =
            *(const float4*)(W + (size_t)(k0 + bk) * 768 + h * DH + bn);
        __syncthreads();
        #pragma unroll
        for (int kk = 0; kk < 16; kk++) {
            float4 a = *(const float4*)&As[kk][tr << 2];
            float4 bv = *(const float4*)&Bs[kk][tc << 2];
            float ar[4] = {a.x, a.y, a.z, a.w};
            float br[4] = {bv.x, bv.y, bv.z, bv.w};
            #pragma unroll
            for (int i = 0; i < 4; i++)
                #pragma unroll
                for (int j = 0; j < 4; j++)
                    acc[i][j] = fmaf(ar[i], br[j], acc[i][j]);
        }
        __syncthreads();
    }
    #pragma unroll
    for (int i = 0; i < 4; i++) {
        int row = m0 + (tr << 2) + i;
        float* cp = OUT + (size_t)row * 768 + h * DH + (tc << 2);
        const float* bb = bias + h * DH + (tc << 2);
        float4 o;
        o.x = acc[i][0] + bb[0]; o.y = acc[i][1] + bb[1];
        o.z = acc[i][2] + bb[2]; o.w = acc[i][3] + bb[3];
        *(float4*)cp = o;
    }
}

// ---------------- launch ------------------------------------------------------
extern "C" void kernel_launch(void* const* d_in, const int* in_sizes, int n_in,
                              void* d_out, int out_size)
{
    const float* q_in  = (const float*)d_in[0];
    const float* k_in  = (const float*)d_in[1];
    const float* v_in  = (const float*)d_in[2];
    const float* kvec  = (const float*)d_in[3];
    const int*   wmask = (const int*)d_in[4];
    const int*   smask = (const int*)d_in[5];
    const float* wq_w = (const float*)d_in[6],  *wq_b = (const float*)d_in[7];
    const float* wk_w = (const float*)d_in[8],  *wk_b = (const float*)d_in[9];
    const float* wv_w = (const float*)d_in[10], *wv_b = (const float*)d_in[11];
    const float* sq_w = (const float*)d_in[12], *sq_b = (const float*)d_in[13];
    const float* sk_w = (const float*)d_in[14], *sk_b = (const float*)d_in[15];
    const float* sv_w = (const float*)d_in[16], *sv_b = (const float*)d_in[17];
    float* out = (float*)d_out;

    float *Qp, *SQ, *Kp, *Vp, *SK, *WH, *P2, *CTX;
    cudaGetSymbolAddress((void**)&Qp,  g_Qp);
    cudaGetSymbolAddress((void**)&SQ,  g_SQ);
    cudaGetSymbolAddress((void**)&Kp,  g_Kp);
    cudaGetSymbolAddress((void**)&Vp,  g_Vp);
    cudaGetSymbolAddress((void**)&SK,  g_SK);
    cudaGetSymbolAddress((void**)&WH,  g_WH);
    cudaGetSymbolAddress((void**)&P2,  g_P2);
    cudaGetSymbolAddress((void**)&CTX, g_CTX);

    cudaFuncSetAttribute(word_attn_kernel,
                         cudaFuncAttributeMaxDynamicSharedMemorySize, WATTN_SMEM);

    GemmJobs jobs;
    jobs.j[0] = { k_in, wk_w, wk_b, Kp, BSZ * NS1 * NS2 };  // 16384 rows
    jobs.j[1] = { v_in, wv_w, wv_b, Vp, BSZ * NS1 * NS2 };  // 16384 rows
    jobs.j[2] = { q_in, wq_w, wq_b, Qp, BSZ * QL };         // 1024 rows
    jobs.j[3] = { q_in, sq_w, sq_b, SQ, BSZ * QL };         // 1024 rows
    jobs.j[4] = { kvec, sk_w, sk_b, SK, BSZ * NS1 };        // 256 rows

    dim3 blk(256);
    // all 5 projections in one launch: grid (n_tiles=6, m_tiles=128, jobs=5)
    sgemm_fused<<<dim3(6, 128, 5), blk>>>(jobs);
    // word attention -> WH
    word_attn_kernel<<<dim3(NHD, NS1, BSZ), blk, WATTN_SMEM>>>(Qp, Kp, Vp, wmask, WH);
    // sentence probs -> P2
    sent_probs_kernel<<<dim3(NHD, BSZ), blk>>>(SQ, SK, smask, P2);
    // ctx = sum_s p2 * wh
    ctx_kernel<<<BSZ * QL, blk>>>(WH, P2, CTX);
    // out = ctx @ sv_w (head-sliced) + sv_b
    final_proj_kernel<<<dim3(16, NHD), blk>>>(CTX, sv_w, sv_b, out);
}

// round 8
// speedup vs baseline: 2.4048x; 1.4437x over previous
#include <cuda_runtime.h>
#include <cstdint>

#define BSZ 8
#define QL  128
#define NS1 32
#define NS2 64
#define HD  768
#define NHD 12
#define DH  64
#define SCALE 0.125f   // 1/sqrt(64)

// ---------------- scratch (device globals; no allocations allowed) ----------
__device__ float g_Qp [BSZ*QL*HD];           // word-attn Q proj
__device__ float g_SQ [BSZ*QL*HD];           // sentence Q proj
__device__ float g_Kp [BSZ*NS1*NS2*HD];      // word K proj
__device__ float g_Vp [BSZ*NS1*NS2*HD];      // word V proj
__device__ float g_SK [BSZ*NS1*HD];          // sentence K proj
__device__ float g_WH [BSZ*QL*NS1*HD];       // word hidden  [b,q,s,768]
__device__ float g_P2 [BSZ*QL*NHD*NS1];      // sentence probs
__device__ float g_CTX[BSZ*QL*NHD*HD];       // ctx = sum_s p2*wh  [b,q,h,768]

// ============================================================================
// Fused projection GEMMs on the tensor pipe (tf32 mma.sync):
//   C[M,768] = A[M,768] @ B[768,768] + bias
// 128x128 block tile, BK=16, 8 warps (2x4), warp tile 64x32 via 4x4 m16n8k8.
// gridDim.y enumerates m-tiles of all 5 jobs back-to-back (no dead blocks).
// ============================================================================
struct GemmJob {
    const float* A;
    const float* B;
    const float* bias;
    float*       C;
    int          start;   // first m-tile index of this job on the y axis
};
struct GemmJobs { GemmJob j[5]; };

__device__ __forceinline__ float tf32r(float x) {
    unsigned u;
    asm("cvt.rna.tf32.f32 %0, %1;" : "=r"(u) : "f"(x));
    return __uint_as_float(u);
}

__device__ __forceinline__ void mma_tf32(float* c, const uint32_t* a, const uint32_t* b) {
    asm volatile(
        "mma.sync.aligned.m16n8k8.row.col.f32.tf32.tf32.f32 "
        "{%0,%1,%2,%3}, {%4,%5,%6,%7}, {%8,%9}, {%0,%1,%2,%3};\n"
        : "+f"(c[0]), "+f"(c[1]), "+f"(c[2]), "+f"(c[3])
        : "r"(a[0]), "r"(a[1]), "r"(a[2]), "r"(a[3]),
          "r"(b[0]), "r"(b[1]));
}

#define SPAD 136   // row pitch: (8*qid + grp) % 32 spans all banks -> conflict-free

__global__ __launch_bounds__(256, 2) void sgemm_tf32(GemmJobs jobs)
{
    const int bt = blockIdx.y;
    int jid = 0;
    #pragma unroll
    for (int j = 1; j < 5; j++) if (bt >= jobs.j[j].start) jid = j;
    const GemmJob jb = jobs.j[jid];
    const int m0 = (bt - jb.start) * 128;
    const int n0 = blockIdx.x * 128;

    __shared__ float As[2][16][SPAD];   // [k][m]
    __shared__ float Bs[2][16][SPAD];   // [k][n]

    const int tid = threadIdx.x;
    // A loader: row lr (0..127), k-range [8*ah, 8*ah+8)
    const int lr = tid & 127, ah = tid >> 7;
    // B loader: k-row kr (0..15), cols [nc, nc+8)
    const int kr = tid >> 4, nc = (tid & 15) << 3;

    const float* aP = jb.A + (size_t)(m0 + lr) * 768 + (ah << 3);
    const float* bP = jb.B + (size_t)kr * 768 + n0 + nc;

    const int lane = tid & 31, grp = lane >> 2, qid = lane & 3;
    const int wid = tid >> 5, wm = wid >> 2, wn = wid & 3;
    const int arow = wm * 64 + grp;
    const int bcol = wn * 32 + grp;

    float acc[4][4][4];
    #pragma unroll
    for (int i = 0; i < 4; i++)
        #pragma unroll
        for (int j = 0; j < 4; j++)
            #pragma unroll
            for (int r = 0; r < 4; r++) acc[i][j][r] = 0.f;

    float4 av0, av1, bv0, bv1;

    // prologue: buffer 0
    av0 = *(const float4*)(aP);
    av1 = *(const float4*)(aP + 4);
    bv0 = *(const float4*)(bP);
    bv1 = *(const float4*)(bP + 4);
    {
        const int kb = ah << 3;
        As[0][kb + 0][lr] = tf32r(av0.x); As[0][kb + 1][lr] = tf32r(av0.y);
        As[0][kb + 2][lr] = tf32r(av0.z); As[0][kb + 3][lr] = tf32r(av0.w);
        As[0][kb + 4][lr] = tf32r(av1.x); As[0][kb + 5][lr] = tf32r(av1.y);
        As[0][kb + 6][lr] = tf32r(av1.z); As[0][kb + 7][lr] = tf32r(av1.w);
        float4 t0 = make_float4(tf32r(bv0.x), tf32r(bv0.y), tf32r(bv0.z), tf32r(bv0.w));
        float4 t1 = make_float4(tf32r(bv1.x), tf32r(bv1.y), tf32r(bv1.z), tf32r(bv1.w));
        *(float4*)&Bs[0][kr][nc]     = t0;
        *(float4*)&Bs[0][kr][nc + 4] = t1;
    }
    __syncthreads();

    int buf = 0;
    for (int k0 = 0; k0 < 768; k0 += 16) {
        const bool more = (k0 + 16) < 768;
        if (more) {
            av0 = *(const float4*)(aP + k0 + 16);
            av1 = *(const float4*)(aP + k0 + 20);
            bv0 = *(const float4*)(bP + (size_t)(k0 + 16) * 768);
            bv1 = *(const float4*)(bP + (size_t)(k0 + 16) * 768 + 4);
        }
        #pragma unroll
        for (int ks = 0; ks < 16; ks += 8) {
            uint32_t a[4][4], b[4][2];
            #pragma unroll
            for (int mi = 0; mi < 4; mi++) {
                const int r = arow + mi * 16;
                a[mi][0] = __float_as_uint(As[buf][ks + qid    ][r]);
                a[mi][1] = __float_as_uint(As[buf][ks + qid    ][r + 8]);
                a[mi][2] = __float_as_uint(As[buf][ks + qid + 4][r]);
                a[mi][3] = __float_as_uint(As[buf][ks + qid + 4][r + 8]);
            }
            #pragma unroll
            for (int nj = 0; nj < 4; nj++) {
                const int c = bcol + nj * 8;
                b[nj][0] = __float_as_uint(Bs[buf][ks + qid    ][c]);
                b[nj][1] = __float_as_uint(Bs[buf][ks + qid + 4][c]);
            }
            #pragma unroll
            for (int mi = 0; mi < 4; mi++)
                #pragma unroll
                for (int nj = 0; nj < 4; nj++)
                    mma_tf32(acc[mi][nj], a[mi], b[nj]);
        }
        if (more) {
            const int nb = buf ^ 1;
            const int kb = ah << 3;
            As[nb][kb + 0][lr] = tf32r(av0.x); As[nb][kb + 1][lr] = tf32r(av0.y);
            As[nb][kb + 2][lr] = tf32r(av0.z); As[nb][kb + 3][lr] = tf32r(av0.w);
            As[nb][kb + 4][lr] = tf32r(av1.x); As[nb][kb + 5][lr] = tf32r(av1.y);
            As[nb][kb + 6][lr] = tf32r(av1.z); As[nb][kb + 7][lr] = tf32r(av1.w);
            float4 t0 = make_float4(tf32r(bv0.x), tf32r(bv0.y), tf32r(bv0.z), tf32r(bv0.w));
            float4 t1 = make_float4(tf32r(bv1.x), tf32r(bv1.y), tf32r(bv1.z), tf32r(bv1.w));
            *(float4*)&Bs[nb][kr][nc]     = t0;
            *(float4*)&Bs[nb][kr][nc + 4] = t1;
        }
        __syncthreads();
        buf ^= 1;
    }

    // epilogue + bias
    #pragma unroll
    for (int mi = 0; mi < 4; mi++) {
        const int r0 = m0 + wm * 64 + mi * 16 + grp;
        #pragma unroll
        for (int nj = 0; nj < 4; nj++) {
            const int c = n0 + wn * 32 + nj * 8 + (qid << 1);
            const float2 bb = *(const float2*)(jb.bias + c);
            float2 o0, o1;
            o0.x = acc[mi][nj][0] + bb.x; o0.y = acc[mi][nj][1] + bb.y;
            o1.x = acc[mi][nj][2] + bb.x; o1.y = acc[mi][nj][3] + bb.y;
            *(float2*)(jb.C + (size_t)r0 * 768 + c)       = o0;
            *(float2*)(jb.C + (size_t)(r0 + 8) * 768 + c) = o1;
        }
    }
}

// ---------------- word attention: one block per (b, s, h) -------------------
#define PADQ 129
#define PADS 65
#define WATTN_SMEM ((64*PADQ + 64*PADS + 64*PADS + 128*PADS) * 4)

__global__ __launch_bounds__(256) void word_attn_kernel(
    const float* __restrict__ Qp, const float* __restrict__ Kp,
    const float* __restrict__ Vp, const int* __restrict__ wmask,
    float* __restrict__ WH)
{
    extern __shared__ float smf[];
    float* Qs = smf;                     // [d][q]  64 x PADQ
    float* Ks = Qs + 64 * PADQ;          // [d][t]  64 x PADS
    float* Vs = Ks + 64 * PADS;          // [t][d]  64 x PADS
    float* S  = Vs + 64 * PADS;          // [q][t] 128 x PADS

    const int h = blockIdx.x, s = blockIdx.y, b = blockIdx.z;
    const int tid = threadIdx.x;

    const float* qbase = Qp + (size_t)b * QL * HD + h * DH;
    for (int idx = tid; idx < QL * DH; idx += 256) {
        int q = idx >> 6, d = idx & 63;
        Qs[d * PADQ + q] = qbase[(size_t)q * HD + d];
    }
    const size_t kvoff = (((size_t)b * NS1 + s) * NS2) * HD + h * DH;
    for (int idx = tid; idx < NS2 * DH; idx += 256) {
        int t = idx >> 6, d = idx & 63;
        size_t g = kvoff + (size_t)t * HD + d;
        Ks[d * PADS + t] = Kp[g];
        Vs[t * PADS + d] = Vp[g];
    }
    __syncthreads();

    const int tr = tid >> 3;   // 0..31 -> q rows tr*4..
    const int tc = tid & 7;    // 0..7  -> t cols tc*8..

    float acc[4][8];
    #pragma unroll
    for (int i = 0; i < 4; i++)
        #pragma unroll
        for (int j = 0; j < 8; j++) acc[i][j] = 0.f;

    for (int d = 0; d < 64; d++) {
        float qr[4], kr[8];
        #pragma unroll
        for (int i = 0; i < 4; i++) qr[i] = Qs[d * PADQ + (tr << 2) + i];
        #pragma unroll
        for (int j = 0; j < 8; j++) kr[j] = Ks[d * PADS + (tc << 3) + j];
        #pragma unroll
        for (int i = 0; i < 4; i++)
            #pragma unroll
            for (int j = 0; j < 8; j++)
                acc[i][j] = fmaf(qr[i], kr[j], acc[i][j]);
    }
    const int* wmrow = wmask + ((size_t)b * NS1 + s) * NS2;
    float wmv[8];
    #pragma unroll
    for (int j = 0; j < 8; j++)
        wmv[j] = (1.f - (float)wmrow[(tc << 3) + j]) * -10000.f;
    #pragma unroll
    for (int i = 0; i < 4; i++)
        #pragma unroll
        for (int j = 0; j < 8; j++)
            S[((tr << 2) + i) * PADS + (tc << 3) + j] = acc[i][j] * SCALE + wmv[j];
    __syncthreads();

    if (tid < 128) {
        float* row = S + tid * PADS;
        float m = row[0];
        #pragma unroll
        for (int t = 1; t < 64; t++) m = fmaxf(m, row[t]);
        float sum = 0.f;
        #pragma unroll
        for (int t = 0; t < 64; t++) { float e = __expf(row[t] - m); row[t] = e; sum += e; }
        float inv = 1.f / sum;
        #pragma unroll
        for (int t = 0; t < 64; t++) row[t] *= inv;
    }
    __syncthreads();

    float o[4][8];
    #pragma unroll
    for (int i = 0; i < 4; i++)
        #pragma unroll
        for (int j = 0; j < 8; j++) o[i][j] = 0.f;
    for (int t = 0; t < 64; t++) {
        float pr[4], vr[8];
        #pragma unroll
        for (int i = 0; i < 4; i++) pr[i] = S[((tr << 2) + i) * PADS + t];
        #pragma unroll
        for (int j = 0; j < 8; j++) vr[j] = Vs[t * PADS + (tc << 3) + j];
        #pragma unroll
        for (int i = 0; i < 4; i++)
            #pragma unroll
            for (int j = 0; j < 8; j++)
                o[i][j] = fmaf(pr[i], vr[j], o[i][j]);
    }
    __syncthreads();
    #pragma unroll
    for (int i = 0; i < 4; i++)
        #pragma unroll
        for (int j = 0; j < 8; j++)
            S[((tr << 2) + i) * PADS + (tc << 3) + j] = o[i][j];
    __syncthreads();

    float* whbase = WH + (((size_t)b * QL) * NS1 + s) * HD + h * DH;
    for (int idx = tid; idx < QL * DH; idx += 256) {
        int q = idx >> 6, d = idx & 63;
        whbase[(size_t)q * NS1 * HD + d] = S[q * PADS + d];
    }
}

// ---------------- sentence probs: block per (h, b) --------------------------
__global__ __launch_bounds__(256) void sent_probs_kernel(
    const float* __restrict__ SQ, const float* __restrict__ SK,
    const int* __restrict__ smask, float* __restrict__ P2)
{
    __shared__ float SKs[32 * 65];
    __shared__ float SQs[8 * 64];
    const int h = blockIdx.x, b = blockIdx.y;
    const int tid = threadIdx.x;

    for (int idx = tid; idx < 32 * 64; idx += 256) {
        int s_ = idx >> 6, d = idx & 63;
        SKs[s_ * 65 + d] = SK[((size_t)b * NS1 + s_) * HD + h * DH + d];
    }
    const int lane = tid & 31, qi = tid >> 5;
    for (int qt = 0; qt < 16; qt++) {
        __syncthreads();
        for (int idx = tid; idx < 8 * 64; idx += 256) {
            int qq = idx >> 6, d = idx & 63;
            SQs[qq * 64 + d] = SQ[((size_t)b * QL + qt * 8 + qq) * HD + h * DH + d];
        }
        __syncthreads();
        int q = qt * 8 + qi;
        float sc = 0.f;
        #pragma unroll
        for (int d = 0; d < 64; d++)
            sc = fmaf(SQs[qi * 64 + d], SKs[lane * 65 + d], sc);
        sc = sc * SCALE +
             (1.f - (float)smask[((size_t)b * QL + q) * NS1 + lane]) * -10000.f;
        float m = sc;
        #pragma unroll
        for (int o = 16; o > 0; o >>= 1) m = fmaxf(m, __shfl_xor_sync(0xffffffffu, m, o));
        float e = __expf(sc - m);
        float sum = e;
        #pragma unroll
        for (int o = 16; o > 0; o >>= 1) sum += __shfl_xor_sync(0xffffffffu, sum, o);
        P2[(((size_t)b * QL + q) * NHD + h) * NS1 + lane] = e / sum;
    }
}

// ---------------- ctx[b,q,h,c] = sum_s p2[b,q,h,s] * wh[b,q,s,c] -------------
// float4 version: 192 threads, each owns 4 contiguous c-columns.
__global__ __launch_bounds__(192) void ctx_kernel(
    const float* __restrict__ WH, const float* __restrict__ P2,
    float* __restrict__ CTX)
{
    __shared__ float p2s[NHD * NS1];
    const int bq = blockIdx.x;   // 0..1023
    const int tid = threadIdx.x; // 0..191
    for (int idx = tid; idx < NHD * NS1; idx += 192)
        p2s[idx] = P2[(size_t)bq * NHD * NS1 + idx];
    __syncthreads();

    const float4* whb = (const float4*)(WH + (size_t)bq * NS1 * HD);  // 192 f4/row
    float4 acc[NHD];
    #pragma unroll
    for (int hh = 0; hh < NHD; hh++) acc[hh] = make_float4(0.f, 0.f, 0.f, 0.f);

    #pragma unroll 4
    for (int s = 0; s < NS1; s++) {
        float4 w = whb[(size_t)s * 192 + tid];
        #pragma unroll
        for (int hh = 0; hh < NHD; hh++) {
            float p = p2s[hh * NS1 + s];
            acc[hh].x = fmaf(p, w.x, acc[hh].x);
            acc[hh].y = fmaf(p, w.y, acc[hh].y);
            acc[hh].z = fmaf(p, w.z, acc[hh].z);
            acc[hh].w = fmaf(p, w.w, acc[hh].w);
        }
    }
    float4* ctxb = (float4*)(CTX + (size_t)bq * NHD * HD);
    #pragma unroll
    for (int hh = 0; hh < NHD; hh++)
        ctxb[(size_t)hh * 192 + tid] = acc[hh];
}

// ---------------- final head-sliced GEMM: block per (mtile, h) --------------
__global__ __launch_bounds__(256) void final_proj_kernel(
    const float* __restrict__ CTX, const float* __restrict__ W,
    const float* __restrict__ bias, float* __restrict__ OUT)
{
    __shared__ float As[16][68];
    __shared__ float Bs[16][64];
    const int tid = threadIdx.x;
    const int tr = tid >> 4;
    const int tc = tid & 15;
    const int m0 = blockIdx.x * 64;
    const int h  = blockIdx.y;

    const int lr = tid >> 2;
    const int lk = (tid & 3) << 2;
    const int bk = tid >> 4;
    const int bn = (tid & 15) << 2;

    float acc[4][4];
    #pragma unroll
    for (int i = 0; i < 4; i++)
        #pragma unroll
        for (int j = 0; j < 4; j++) acc[i][j] = 0.f;

    for (int k0 = 0; k0 < 768; k0 += 16) {
        float4 av = *(const float4*)(CTX + (size_t)(m0 + lr) * (NHD * HD) + h * HD + k0 + lk);
        As[lk + 0][lr] = av.x; As[lk + 1][lr] = av.y;
        As[lk + 2][lr] = av.z; As[lk + 3][lr] = av.w;
        *(float4*)&Bs[bk][bn] =
            *(const float4*)(W + (size_t)(k0 + bk) * 768 + h * DH + bn);
        __syncthreads();
        #pragma unroll
        for (int kk = 0; kk < 16; kk++) {
            float4 a = *(const float4*)&As[kk][tr << 2];
            float4 bv = *(const float4*)&Bs[kk][tc << 2];
            float ar[4] = {a.x, a.y, a.z, a.w};
            float br[4] = {bv.x, bv.y, bv.z, bv.w};
            #pragma unroll
            for (int i = 0; i < 4; i++)
                #pragma unroll
                for (int j = 0; j < 4; j++)
                    acc[i][j] = fmaf(ar[i], br[j], acc[i][j]);
        }
        __syncthreads();
    }
    #pragma unroll
    for (int i = 0; i < 4; i++) {
        int row = m0 + (tr << 2) + i;
        float* cp = OUT + (size_t)row * 768 + h * DH + (tc << 2);
        const float* bb = bias + h * DH + (tc << 2);
        float4 o;
        o.x = acc[i][0] + bb[0]; o.y = acc[i][1] + bb[1];
        o.z = acc[i][2] + bb[2]; o.w = acc[i][3] + bb[3];
        *(float4*)cp = o;
    }
}

// ---------------- launch ------------------------------------------------------
extern "C" void kernel_launch(void* const* d_in, const int* in_sizes, int n_in,
                              void* d_out, int out_size)
{
    const float* q_in  = (const float*)d_in[0];
    const float* k_in  = (const float*)d_in[1];
    const float* v_in  = (const float*)d_in[2];
    const float* kvec  = (const float*)d_in[3];
    const int*   wmask = (const int*)d_in[4];
    const int*   smask = (const int*)d_in[5];
    const float* wq_w = (const float*)d_in[6],  *wq_b = (const float*)d_in[7];
    const float* wk_w = (const float*)d_in[8],  *wk_b = (const float*)d_in[9];
    const float* wv_w = (const float*)d_in[10], *wv_b = (const float*)d_in[11];
    const float* sq_w = (const float*)d_in[12], *sq_b = (const float*)d_in[13];
    const float* sk_w = (const float*)d_in[14], *sk_b = (const float*)d_in[15];
    const float* sv_w = (const float*)d_in[16], *sv_b = (const float*)d_in[17];
    float* out = (float*)d_out;

    float *Qp, *SQ, *Kp, *Vp, *SK, *WH, *P2, *CTX;
    cudaGetSymbolAddress((void**)&Qp,  g_Qp);
    cudaGetSymbolAddress((void**)&SQ,  g_SQ);
    cudaGetSymbolAddress((void**)&Kp,  g_Kp);
    cudaGetSymbolAddress((void**)&Vp,  g_Vp);
    cudaGetSymbolAddress((void**)&SK,  g_SK);
    cudaGetSymbolAddress((void**)&WH,  g_WH);
    cudaGetSymbolAddress((void**)&P2,  g_P2);
    cudaGetSymbolAddress((void**)&CTX, g_CTX);

    cudaFuncSetAttribute(word_attn_kernel,
                         cudaFuncAttributeMaxDynamicSharedMemorySize, WATTN_SMEM);

    // m-tile layout on gridDim.y: K[0,128) V[128,256) Q[256,264) SQ[264,272) SK[272,274)
    GemmJobs jobs;
    jobs.j[0] = { k_in, wk_w, wk_b, Kp, 0   };
    jobs.j[1] = { v_in, wv_w, wv_b, Vp, 128 };
    jobs.j[2] = { q_in, wq_w, wq_b, Qp, 256 };
    jobs.j[3] = { q_in, sq_w, sq_b, SQ, 264 };
    jobs.j[4] = { kvec, sk_w, sk_b, SK, 272 };

    dim3 blk(256);
    sgemm_tf32<<<dim3(6, 274), blk>>>(jobs);
    word_attn_kernel<<<dim3(NHD, NS1, BSZ), blk, WATTN_SMEM>>>(Qp, Kp, Vp, wmask, WH);
    sent_probs_kernel<<<dim3(NHD, BSZ), blk>>>(SQ, SK, smask, P2);
    ctx_kernel<<<BSZ * QL, 192>>>(WH, P2, CTX);
    final_proj_kernel<<<dim3(16, NHD), blk>>>(CTX, sv_w, sv_b, out);
}

// round 13
// speedup vs baseline: 3.1105x; 1.2934x over previous
#include <cuda_runtime.h>
#include <cstdint>

#define BSZ 8
#define QL  128
#define NS1 32
#define NS2 64
#define HD  768
#define NHD 12
#define DH  64
#define SCALE 0.125f   // 1/sqrt(64)

// ---------------- scratch (device globals; no allocations allowed) ----------
__device__ float g_Qp [BSZ*QL*HD];           // word-attn Q proj
__device__ float g_SQ [BSZ*QL*HD];           // sentence Q proj
__device__ float g_Kp [BSZ*NS1*NS2*HD];      // word K proj
__device__ float g_Vp [BSZ*NS1*NS2*HD];      // word V proj
__device__ float g_SK [BSZ*NS1*HD];          // sentence K proj
__device__ float g_WH [BSZ*QL*NS1*HD];       // word hidden  [b,q,s,768]
__device__ float g_P2 [BSZ*QL*NHD*NS1];      // sentence probs
__device__ float g_CTX[BSZ*QL*NHD*HD];       // ctx = sum_s p2*wh  [b,q,h,768]

// ---------------- helpers ----------------------------------------------------
__device__ __forceinline__ float tf32r(float x) {
    unsigned u;
    asm("cvt.rna.tf32.f32 %0, %1;" : "=r"(u) : "f"(x));
    return __uint_as_float(u);
}
__device__ __forceinline__ void mma_tf32(float* c, const uint32_t* a, const uint32_t* b) {
    asm volatile(
        "mma.sync.aligned.m16n8k8.row.col.f32.tf32.tf32.f32 "
        "{%0,%1,%2,%3}, {%4,%5,%6,%7}, {%8,%9}, {%0,%1,%2,%3};\n"
        : "+f"(c[0]), "+f"(c[1]), "+f"(c[2]), "+f"(c[3])
        : "r"(a[0]), "r"(a[1]), "r"(a[2]), "r"(a[3]),
          "r"(b[0]), "r"(b[1]));
}
__device__ __forceinline__ void cpa16(void* s, const void* g) {
    unsigned sa = (unsigned)__cvta_generic_to_shared(s);
    asm volatile("cp.async.cg.shared.global [%0], [%1], 16;\n" :: "r"(sa), "l"(g));
}
__device__ __forceinline__ void cpa_commit() {
    asm volatile("cp.async.commit_group;\n" ::: "memory");
}

// ============================================================================
// Fused projection GEMMs (tf32 mma.sync): C[M,768] = A[M,768]@B[768,768]+bias
// ============================================================================
struct GemmJob {
    const float* A;
    const float* B;
    const float* bias;
    float*       C;
    int          start;   // first m-tile index of this job on the y axis
};
struct GemmJobs { GemmJob j[5]; };

#define SPAD 136   // pitch: (8*qid + grp) mod 32 spans all banks -> conflict-free

__global__ __launch_bounds__(256, 2) void sgemm_tf32(GemmJobs jobs)
{
    const int bt = blockIdx.y;
    int jid = 0;
    #pragma unroll
    for (int j = 1; j < 5; j++) if (bt >= jobs.j[j].start) jid = j;
    const GemmJob jb = jobs.j[jid];
    const int m0 = (bt - jb.start) * 128;
    const int n0 = blockIdx.x * 128;

    __shared__ float As[2][16][SPAD];   // [k][m]
    __shared__ float Bs[2][16][SPAD];   // [k][n]

    const int tid = threadIdx.x;
    const int lr = tid & 127, ah = tid >> 7;
    const int kr = tid >> 4, nc = (tid & 15) << 3;

    const float* aP = jb.A + (size_t)(m0 + lr) * 768 + (ah << 3);
    const float* bP = jb.B + (size_t)kr * 768 + n0 + nc;

    const int lane = tid & 31, grp = lane >> 2, qid = lane & 3;
    const int wid = tid >> 5, wm = wid >> 2, wn = wid & 3;
    const int arow = wm * 64 + grp;
    const int bcol = wn * 32 + grp;

    float acc[4][4][4];
    #pragma unroll
    for (int i = 0; i < 4; i++)
        #pragma unroll
        for (int j = 0; j < 4; j++)
            #pragma unroll
            for (int r = 0; r < 4; r++) acc[i][j][r] = 0.f;

    float4 av0, av1, bv0, bv1;

    av0 = *(const float4*)(aP);
    av1 = *(const float4*)(aP + 4);
    bv0 = *(const float4*)(bP);
    bv1 = *(const float4*)(bP + 4);
    {
        const int kb = ah << 3;
        As[0][kb + 0][lr] = tf32r(av0.x); As[0][kb + 1][lr] = tf32r(av0.y);
        As[0][kb + 2][lr] = tf32r(av0.z); As[0][kb + 3][lr] = tf32r(av0.w);
        As[0][kb + 4][lr] = tf32r(av1.x); As[0][kb + 5][lr] = tf32r(av1.y);
        As[0][kb + 6][lr] = tf32r(av1.z); As[0][kb + 7][lr] = tf32r(av1.w);
        float4 t0 = make_float4(tf32r(bv0.x), tf32r(bv0.y), tf32r(bv0.z), tf32r(bv0.w));
        float4 t1 = make_float4(tf32r(bv1.x), tf32r(bv1.y), tf32r(bv1.z), tf32r(bv1.w));
        *(float4*)&Bs[0][kr][nc]     = t0;
        *(float4*)&Bs[0][kr][nc + 4] = t1;
    }
    __syncthreads();

    int buf = 0;
    for (int k0 = 0; k0 < 768; k0 += 16) {
        const bool more = (k0 + 16) < 768;
        if (more) {
            av0 = *(const float4*)(aP + k0 + 16);
            av1 = *(const float4*)(aP + k0 + 20);
            bv0 = *(const float4*)(bP + (size_t)(k0 + 16) * 768);
            bv1 = *(const float4*)(bP + (size_t)(k0 + 16) * 768 + 4);
        }
        #pragma unroll
        for (int ks = 0; ks < 16; ks += 8) {
            uint32_t a[4][4], b[4][2];
            #pragma unroll
            for (int mi = 0; mi < 4; mi++) {
                const int r = arow + mi * 16;
                a[mi][0] = __float_as_uint(As[buf][ks + qid    ][r]);
                a[mi][1] = __float_as_uint(As[buf][ks + qid    ][r + 8]);
                a[mi][2] = __float_as_uint(As[buf][ks + qid + 4][r]);
                a[mi][3] = __float_as_uint(As[buf][ks + qid + 4][r + 8]);
            }
            #pragma unroll
            for (int nj = 0; nj < 4; nj++) {
                const int c = bcol + nj * 8;
                b[nj][0] = __float_as_uint(Bs[buf][ks + qid    ][c]);
                b[nj][1] = __float_as_uint(Bs[buf][ks + qid + 4][c]);
            }
            #pragma unroll
            for (int mi = 0; mi < 4; mi++)
                #pragma unroll
                for (int nj = 0; nj < 4; nj++)
                    mma_tf32(acc[mi][nj], a[mi], b[nj]);
        }
        if (more) {
            const int nb = buf ^ 1;
            const int kb = ah << 3;
            As[nb][kb + 0][lr] = tf32r(av0.x); As[nb][kb + 1][lr] = tf32r(av0.y);
            As[nb][kb + 2][lr] = tf32r(av0.z); As[nb][kb + 3][lr] = tf32r(av0.w);
            As[nb][kb + 4][lr] = tf32r(av1.x); As[nb][kb + 5][lr] = tf32r(av1.y);
            As[nb][kb + 6][lr] = tf32r(av1.z); As[nb][kb + 7][lr] = tf32r(av1.w);
            float4 t0 = make_float4(tf32r(bv0.x), tf32r(bv0.y), tf32r(bv0.z), tf32r(bv0.w));
            float4 t1 = make_float4(tf32r(bv1.x), tf32r(bv1.y), tf32r(bv1.z), tf32r(bv1.w));
            *(float4*)&Bs[nb][kr][nc]     = t0;
            *(float4*)&Bs[nb][kr][nc + 4] = t1;
        }
        __syncthreads();
        buf ^= 1;
    }

    #pragma unroll
    for (int mi = 0; mi < 4; mi++) {
        const int r0 = m0 + wm * 64 + mi * 16 + grp;
        #pragma unroll
        for (int nj = 0; nj < 4; nj++) {
            const int c = n0 + wn * 32 + nj * 8 + (qid << 1);
            const float2 bb = *(const float2*)(jb.bias + c);
            float2 o0, o1;
            o0.x = acc[mi][nj][0] + bb.x; o0.y = acc[mi][nj][1] + bb.y;
            o1.x = acc[mi][nj][2] + bb.x; o1.y = acc[mi][nj][3] + bb.y;
            *(float2*)(jb.C + (size_t)r0 * 768 + c)       = o0;
            *(float2*)(jb.C + (size_t)(r0 + 8) * 768 + c) = o1;
        }
    }
}

// ============================================================================
// Word attention on the tensor pipe. One block per (b, s, h), 256 thr, 8 warps.
//  Phase 1: S^T[t][q] = K[t,:] . Q[q,:]  (A = K natural, B = Q^T in smem)
//  Phase 2: softmax over t per q-row
//  Phase 3: O[q][d] = P[q,:] . V[:,d]   (A = P from smem, B = V natural)
// Pitches: fragment LDS bank = (8*qid + grp) or (4*grp + qid) mod 32 -> clean.
// ============================================================================
#define KSP 68
#define QSP 136     // [d][q]: q runs 0..127 -> pitch must exceed 128 (R12 bug fix)
#define VSP 72
#define PSP 68
#define OFF_KS 0
#define OFF_QS (64*KSP)
#define OFF_VS (OFF_QS + 64*QSP)
#define OFF_PS (OFF_VS + 64*VSP)
#define OFF_WM (OFF_PS + 128*PSP)
#define WATTN_BYTES ((OFF_WM + 64) * 4)

__global__ __launch_bounds__(256, 2) void word_attn_mma(
    const float* __restrict__ Qp, const float* __restrict__ Kp,
    const float* __restrict__ Vp, const int* __restrict__ wmask,
    float* __restrict__ WH)
{
    extern __shared__ float sm[];
    float* Ks  = sm + OFF_KS;   // [t][d] pitch 68
    float* Qs  = sm + OFF_QS;   // [d][q] pitch 136
    float* Vs  = sm + OFF_VS;   // [t][d] pitch 72
    float* Ps  = sm + OFF_PS;   // [q][t] pitch 68
    float* wmf = sm + OFF_WM;

    const int h = blockIdx.x, s = blockIdx.y, b = blockIdx.z;
    const int tid = threadIdx.x, lane = tid & 31, wid = tid >> 5;
    const int grp = lane >> 2, qid = lane & 3;

    // K,V natural [t][d], tf32-rounded (coalesced gmem)
    const size_t kvoff = (((size_t)b * NS1 + s) * NS2) * HD + h * DH;
    for (int idx = tid; idx < NS2 * 16; idx += 256) {
        int t = idx >> 4, dq = (idx & 15) << 2;
        float4 kv = *(const float4*)(Kp + kvoff + (size_t)t * HD + dq);
        float4 vv = *(const float4*)(Vp + kvoff + (size_t)t * HD + dq);
        Ks[t * KSP + dq + 0] = tf32r(kv.x); Ks[t * KSP + dq + 1] = tf32r(kv.y);
        Ks[t * KSP + dq + 2] = tf32r(kv.z); Ks[t * KSP + dq + 3] = tf32r(kv.w);
        Vs[t * VSP + dq + 0] = tf32r(vv.x); Vs[t * VSP + dq + 1] = tf32r(vv.y);
        Vs[t * VSP + dq + 2] = tf32r(vv.z); Vs[t * VSP + dq + 3] = tf32r(vv.w);
    }
    // Q transposed into Qs[d][q]; Qp is L2-resident so scattered reads are cheap.
    const float* qbase = Qp + (size_t)b * QL * HD + h * DH;
    for (int idx = tid; idx < QL * 16; idx += 256) {
        int q = idx & 127, dq = (idx >> 7) << 2;
        float4 qv = *(const float4*)(qbase + (size_t)q * HD + dq);
        Qs[(dq + 0) * QSP + q] = tf32r(qv.x);
        Qs[(dq + 1) * QSP + q] = tf32r(qv.y);
        Qs[(dq + 2) * QSP + q] = tf32r(qv.z);
        Qs[(dq + 3) * QSP + q] = tf32r(qv.w);
    }
    if (tid < 64)
        wmf[tid] = (1.f - (float)wmask[((size_t)b * NS1 + s) * NS2 + tid]) * -10000.f;
    __syncthreads();

    // ---- Phase 1: S^T = K . Q^T  (M=64 t, N=128 q) -> Ps[q][t]
    {
        const int wm = wid & 3, wn = wid >> 2;
        const int trow = wm * 16 + grp;
        float sacc[8][4];
        #pragma unroll
        for (int nj = 0; nj < 8; nj++)
            #pragma unroll
            for (int r = 0; r < 4; r++) sacc[nj][r] = 0.f;

        #pragma unroll
        for (int kc = 0; kc < 8; kc++) {
            uint32_t a[4];
            a[0] = __float_as_uint(Ks[trow * KSP + 8 * kc + qid]);
            a[1] = __float_as_uint(Ks[(trow + 8) * KSP + 8 * kc + qid]);
            a[2] = __float_as_uint(Ks[trow * KSP + 8 * kc + qid + 4]);
            a[3] = __float_as_uint(Ks[(trow + 8) * KSP + 8 * kc + qid + 4]);
            #pragma unroll
            for (int nj = 0; nj < 8; nj++) {
                const int qc = wn * 64 + nj * 8 + grp;
                uint32_t bb[2];
                bb[0] = __float_as_uint(Qs[(8 * kc + qid) * QSP + qc]);
                bb[1] = __float_as_uint(Qs[(8 * kc + qid + 4) * QSP + qc]);
                mma_tf32(sacc[nj], a, bb);
            }
        }
        #pragma unroll
        for (int nj = 0; nj < 8; nj++) {
            const int q0 = wn * 64 + nj * 8 + 2 * qid;
            Ps[q0 * PSP + trow]           = sacc[nj][0];
            Ps[(q0 + 1) * PSP + trow]     = sacc[nj][1];
            Ps[q0 * PSP + trow + 8]       = sacc[nj][2];
            Ps[(q0 + 1) * PSP + trow + 8] = sacc[nj][3];
        }
    }
    __syncthreads();

    // ---- Phase 2: softmax per q row (2 lanes per row)
    {
        const int q = tid >> 1, half = (tid & 1) * 32;
        float* row = Ps + q * PSP + half;
        const float* wm2 = wmf + half;
        float v[32];
        float m = -1e30f;
        #pragma unroll
        for (int i = 0; i < 32; i++) {
            v[i] = row[i] * SCALE + wm2[i];
            m = fmaxf(m, v[i]);
        }
        m = fmaxf(m, __shfl_xor_sync(0xffffffffu, m, 1));
        float sum = 0.f;
        #pragma unroll
        for (int i = 0; i < 32; i++) { v[i] = __expf(v[i] - m); sum += v[i]; }
        sum += __shfl_xor_sync(0xffffffffu, sum, 1);
        const float inv = 1.f / sum;
        #pragma unroll
        for (int i = 0; i < 32; i++) row[i] = tf32r(v[i] * inv);
    }
    __syncthreads();

    // ---- Phase 3: O = P . V  (M=128 q, N=64 d)
    {
        const int r0 = wid * 16 + grp;
        float oacc[8][4];
        #pragma unroll
        for (int nj = 0; nj < 8; nj++)
            #pragma unroll
            for (int r = 0; r < 4; r++) oacc[nj][r] = 0.f;

        #pragma unroll
        for (int kc = 0; kc < 8; kc++) {
            uint32_t a[4];
            a[0] = __float_as_uint(Ps[r0 * PSP + 8 * kc + qid]);
            a[1] = __float_as_uint(Ps[(r0 + 8) * PSP + 8 * kc + qid]);
            a[2] = __float_as_uint(Ps[r0 * PSP + 8 * kc + qid + 4]);
            a[3] = __float_as_uint(Ps[(r0 + 8) * PSP + 8 * kc + qid + 4]);
            #pragma unroll
            for (int nj = 0; nj < 8; nj++) {
                uint32_t bb[2];
                bb[0] = __float_as_uint(Vs[(8 * kc + qid) * VSP + nj * 8 + grp]);
                bb[1] = __float_as_uint(Vs[(8 * kc + qid + 4) * VSP + nj * 8 + grp]);
                mma_tf32(oacc[nj], a, bb);
            }
        }
        // WH[((b*128+q)*32+s)*768 + h*64 + d]
        float* wh0 = WH + (((size_t)(b * QL + r0)) * NS1 + s) * HD + h * DH;
        float* wh1 = wh0 + (size_t)8 * NS1 * HD;
        #pragma unroll
        for (int nj = 0; nj < 8; nj++) {
            float2 x0 = make_float2(oacc[nj][0], oacc[nj][1]);
            float2 x1 = make_float2(oacc[nj][2], oacc[nj][3]);
            *(float2*)(wh0 + nj * 8 + 2 * qid) = x0;
            *(float2*)(wh1 + nj * 8 + 2 * qid) = x1;
        }
    }
}

// ---------------- sentence probs: block per (h, b) --------------------------
__global__ __launch_bounds__(256) void sent_probs_kernel(
    const float* __restrict__ SQ, const float* __restrict__ SK,
    const int* __restrict__ smask, float* __restrict__ P2)
{
    __shared__ float SKs[32 * 65];
    __shared__ float SQs[8 * 64];
    const int h = blockIdx.x, b = blockIdx.y;
    const int tid = threadIdx.x;

    for (int idx = tid; idx < 32 * 64; idx += 256) {
        int s_ = idx >> 6, d = idx & 63;
        SKs[s_ * 65 + d] = SK[((size_t)b * NS1 + s_) * HD + h * DH + d];
    }
    const int lane = tid & 31, qi = tid >> 5;
    for (int qt = 0; qt < 16; qt++) {
        __syncthreads();
        for (int idx = tid; idx < 8 * 64; idx += 256) {
            int qq = idx >> 6, d = idx & 63;
            SQs[qq * 64 + d] = SQ[((size_t)b * QL + qt * 8 + qq) * HD + h * DH + d];
        }
        __syncthreads();
        int q = qt * 8 + qi;
        float sc = 0.f;
        #pragma unroll
        for (int d = 0; d < 64; d++)
            sc = fmaf(SQs[qi * 64 + d], SKs[lane * 65 + d], sc);
        sc = sc * SCALE +
             (1.f - (float)smask[((size_t)b * QL + q) * NS1 + lane]) * -10000.f;
        float m = sc;
        #pragma unroll
        for (int o = 16; o > 0; o >>= 1) m = fmaxf(m, __shfl_xor_sync(0xffffffffu, m, o));
        float e = __expf(sc - m);
        float sum = e;
        #pragma unroll
        for (int o = 16; o > 0; o >>= 1) sum += __shfl_xor_sync(0xffffffffu, sum, o);
        P2[(((size_t)b * QL + q) * NHD + h) * NS1 + lane] = e / sum;
    }
}

// ---------------- ctx[b,q,h,c] = sum_s p2[b,q,h,s] * wh[b,q,s,c] -------------
// cp.async pipelined: 4 WH rows per stage, double buffered.
__global__ __launch_bounds__(192) void ctx_kernel(
    const float* __restrict__ WH, const float* __restrict__ P2,
    float* __restrict__ CTX)
{
    __shared__ float p2s[NHD * NS1];
    __shared__ float4 wbuf[2][4][192];   // 24 KB
    const int bq = blockIdx.x;
    const int tid = threadIdx.x;
    for (int idx = tid; idx < NHD * NS1; idx += 192)
        p2s[idx] = P2[(size_t)bq * NHD * NS1 + idx];

    const float4* whb = (const float4*)(WH + (size_t)bq * NS1 * HD);  // 192 f4/row

    #pragma unroll
    for (int r = 0; r < 4; r++)
        cpa16(&wbuf[0][r][tid], &whb[(size_t)r * 192 + tid]);
    cpa_commit();

    float4 acc[NHD];
    #pragma unroll
    for (int hh = 0; hh < NHD; hh++) acc[hh] = make_float4(0.f, 0.f, 0.f, 0.f);

    for (int st = 0; st < 8; st++) {
        if (st < 7) {
            #pragma unroll
            for (int r = 0; r < 4; r++)
                cpa16(&wbuf[(st + 1) & 1][r][tid],
                      &whb[(size_t)((st + 1) * 4 + r) * 192 + tid]);
            cpa_commit();
            asm volatile("cp.async.wait_group 1;\n" ::: "memory");
        } else {
            asm volatile("cp.async.wait_group 0;\n" ::: "memory");
        }
        __syncthreads();
        #pragma unroll
        for (int r = 0; r < 4; r++) {
            float4 w = wbuf[st & 1][r][tid];
            const int s = st * 4 + r;
            #pragma unroll
            for (int hh = 0; hh < NHD; hh++) {
                float p = p2s[hh * NS1 + s];
                acc[hh].x = fmaf(p, w.x, acc[hh].x);
                acc[hh].y = fmaf(p, w.y, acc[hh].y);
                acc[hh].z = fmaf(p, w.z, acc[hh].z);
                acc[hh].w = fmaf(p, w.w, acc[hh].w);
            }
        }
        __syncthreads();
    }
    float4* ctxb = (float4*)(CTX + (size_t)bq * NHD * HD);
    #pragma unroll
    for (int hh = 0; hh < NHD; hh++)
        ctxb[(size_t)hh * 192 + tid] = acc[hh];
}

// ---------------- final head-sliced GEMM: block per (mtile, h) --------------
__global__ __launch_bounds__(256) void final_proj_kernel(
    const float* __restrict__ CTX, const float* __restrict__ W,
    const float* __restrict__ bias, float* __restrict__ OUT)
{
    __shared__ float As[16][68];
    __shared__ float Bs[16][64];
    const int tid = threadIdx.x;
    const int tr = tid >> 4;
    const int tc = tid & 15;
    const int m0 = blockIdx.x * 64;
    const int h  = blockIdx.y;

    const int lr = tid >> 2;
    const int lk = (tid & 3) << 2;
    const int bk = tid >> 4;
    const int bn = (tid & 15) << 2;

    float acc[4][4];
    #pragma unroll
    for (int i = 0; i < 4; i++)
        #pragma unroll
        for (int j = 0; j < 4; j++) acc[i][j] = 0.f;

    for (int k0 = 0; k0 < 768; k0 += 16) {
        float4 av = *(const float4*)(CTX + (size_t)(m0 + lr) * (NHD * HD) + h * HD + k0 + lk);
        As[lk + 0][lr] = av.x; As[lk + 1][lr] = av.y;
        As[lk + 2][lr] = av.z; As[lk + 3][lr] = av.w;
        *(float4*)&Bs[bk][bn] =
            *(const float4*)(W + (size_t)(k0 + bk) * 768 + h * DH + bn);
        __syncthreads();
        #pragma unroll
        for (int kk = 0; kk < 16; kk++) {
            float4 a = *(const float4*)&As[kk][tr << 2];
            float4 bv = *(const float4*)&Bs[kk][tc << 2];
            float ar[4] = {a.x, a.y, a.z, a.w};
            float br[4] = {bv.x, bv.y, bv.z, bv.w};
            #pragma unroll
            for (int i = 0; i < 4; i++)
                #pragma unroll
                for (int j = 0; j < 4; j++)
                    acc[i][j] = fmaf(ar[i], br[j], acc[i][j]);
        }
        __syncthreads();
    }
    #pragma unroll
    for (int i = 0; i < 4; i++) {
        int row = m0 + (tr << 2) + i;
        float* cp = OUT + (size_t)row * 768 + h * DH + (tc << 2);
        const float* bb = bias + h * DH + (tc << 2);
        float4 o;
        o.x = acc[i][0] + bb[0]; o.y = acc[i][1] + bb[1];
        o.z = acc[i][2] + bb[2]; o.w = acc[i][3] + bb[3];
        *(float4*)cp = o;
    }
}

// ---------------- launch ------------------------------------------------------
extern "C" void kernel_launch(void* const* d_in, const int* in_sizes, int n_in,
                              void* d_out, int out_size)
{
    const float* q_in  = (const float*)d_in[0];
    const float* k_in  = (const float*)d_in[1];
    const float* v_in  = (const float*)d_in[2];
    const float* kvec  = (const float*)d_in[3];
    const int*   wmask = (const int*)d_in[4];
    const int*   smask = (const int*)d_in[5];
    const float* wq_w = (const float*)d_in[6],  *wq_b = (const float*)d_in[7];
    const float* wk_w = (const float*)d_in[8],  *wk_b = (const float*)d_in[9];
    const float* wv_w = (const float*)d_in[10], *wv_b = (const float*)d_in[11];
    const float* sq_w = (const float*)d_in[12], *sq_b = (const float*)d_in[13];
    const float* sk_w = (const float*)d_in[14], *sk_b = (const float*)d_in[15];
    const float* sv_w = (const float*)d_in[16], *sv_b = (const float*)d_in[17];
    float* out = (float*)d_out;

    float *Qp, *SQ, *Kp, *Vp, *SK, *WH, *P2, *CTX;
    cudaGetSymbolAddress((void**)&Qp,  g_Qp);
    cudaGetSymbolAddress((void**)&SQ,  g_SQ);
    cudaGetSymbolAddress((void**)&Kp,  g_Kp);
    cudaGetSymbolAddress((void**)&Vp,  g_Vp);
    cudaGetSymbolAddress((void**)&SK,  g_SK);
    cudaGetSymbolAddress((void**)&WH,  g_WH);
    cudaGetSymbolAddress((void**)&P2,  g_P2);
    cudaGetSymbolAddress((void**)&CTX, g_CTX);

    cudaFuncSetAttribute(word_attn_mma,
                         cudaFuncAttributeMaxDynamicSharedMemorySize, WATTN_BYTES);

    // m-tile layout on gridDim.y: K[0,128) V[128,256) Q[256,264) SQ[264,272) SK[272,274)
    GemmJobs jobs;
    jobs.j[0] = { k_in, wk_w, wk_b, Kp, 0   };
    jobs.j[1] = { v_in, wv_w, wv_b, Vp, 128 };
    jobs.j[2] = { q_in, wq_w, wq_b, Qp, 256 };
    jobs.j[3] = { q_in, sq_w, sq_b, SQ, 264 };
    jobs.j[4] = { kvec, sk_w, sk_b, SK, 272 };

    dim3 blk(256);
    sgemm_tf32<<<dim3(6, 274), blk>>>(jobs);
    word_attn_mma<<<dim3(NHD, NS1, BSZ), blk, WATTN_BYTES>>>(Qp, Kp, Vp, wmask, WH);
    sent_probs_kernel<<<dim3(NHD, BSZ), blk>>>(SQ, SK, smask, P2);
    ctx_kernel<<<BSZ * QL, 192>>>(WH, P2, CTX);
    final_proj_kernel<<<dim3(16, NHD), blk>>>(CTX, sv_w, sv_b, out);
}